// round 8
// baseline (speedup 1.0000x reference)
#include <cuda_runtime.h>
#include <math.h>

// ---------------- constants ----------------
#define VOX   2097152          // 128^3
#define CCH   48               // feature channels
#define NPOS  4736             // 4096 + 512 + 128(pad) positions per batch
#define NGRAM 1078             // 2*528 + 2*10 + 2*1 gram tiles
#define NDICE 2048

// ---------------- device scratch ----------------
__device__ float g_dpart[NDICE * 9];      // dice per-block partials
__device__ float g_gpart[NGRAM * 9];      // gram per-block partials
__device__ float g_fnorm[2 * NPOS * CCH];
__device__ int   g_cls[2 * NPOS];
__device__ unsigned int g_ticket;

// ================= kernel A: fused dice + prep =================
__global__ void __launch_bounds__(256)
diceprep_kernel(const float* __restrict__ pred, const int* __restrict__ tgt,
                const float* __restrict__ f0, const float* __restrict__ f1,
                const float* __restrict__ f2) {
    int bid = blockIdx.x;
    if (bid == 0 && threadIdx.x == 0) g_ticket = 0;   // reset finalize ticket
    if (bid < NDICE) {
        const int b = bid >> 10;
        const int chunk = bid & 1023;
        const int Q = VOX / 4;
        float fi0 = 0.f, fi1 = 0.f, fi2 = 0.f;
        float fp0 = 0.f, fp1 = 0.f, fp2 = 0.f;
        float fc0 = 0.f, fc1 = 0.f, fc2 = 0.f;
        const float4* P  = (const float4*)pred;
        const int4*   T4 = (const int4*)tgt;

        for (int q = chunk * 256 + threadIdx.x; q < Q; q += 1024 * 256) {
            float4 x0 = P[(size_t)(b * 3 + 0) * Q + q];
            float4 x1 = P[(size_t)(b * 3 + 1) * Q + q];
            float4 x2 = P[(size_t)(b * 3 + 2) * Q + q];
            int4   tv = T4[(size_t)b * Q + q];

#define DO_VOXEL(pa, pb, pc, tt)                                           \
            {                                                              \
                float e0 = __expf(pa);                                     \
                float e1 = __expf(pb);                                     \
                float e2 = __expf(pc);                                     \
                float inv = __fdividef(1.f, e0 + e1 + e2);                 \
                e0 *= inv; e1 *= inv; e2 *= inv;                           \
                fp0 += e0; fp1 += e1; fp2 += e2;                           \
                int tc = (tt) < 0 ? 0 : (tt);                              \
                if (tc == 0)      { fi0 += e0; fc0 += 1.f; }               \
                else if (tc == 1) { fi1 += e1; fc1 += 1.f; }               \
                else              { fi2 += e2; fc2 += 1.f; }               \
            }
            DO_VOXEL(x0.x, x1.x, x2.x, tv.x);
            DO_VOXEL(x0.y, x1.y, x2.y, tv.y);
            DO_VOXEL(x0.z, x1.z, x2.z, tv.z);
            DO_VOXEL(x0.w, x1.w, x2.w, tv.w);
#undef DO_VOXEL
        }

        float v[9] = { fi0, fi1, fi2, fp0, fp1, fp2, fc0, fc1, fc2 };
#pragma unroll
        for (int o = 16; o; o >>= 1)
#pragma unroll
            for (int q = 0; q < 9; q++)
                v[q] += __shfl_down_sync(0xffffffffu, v[q], o);

        __shared__ float red[8][9];
        int w = threadIdx.x >> 5, l = threadIdx.x & 31;
        if (l == 0)
#pragma unroll
            for (int q = 0; q < 9; q++) red[w][q] = v[q];
        __syncthreads();
        if (threadIdx.x < 9) {
            float s = 0.f;
#pragma unroll
            for (int w2 = 0; w2 < 8; w2++) s += red[w2][threadIdx.x];
            g_dpart[bid * 9 + threadIdx.x] = s;
        }
    } else {
        int gid = (bid - NDICE) * 256 + threadIdx.x;
        if (gid >= 2 * NPOS) return;
        int b = gid / NPOS, idx = gid % NPOS;
        const float* fmap;
        int D, s, N, n;
        if (idx < 4096)      { fmap = f0; D = 16; s = 8;  N = 4096; n = idx; }
        else if (idx < 4608) { fmap = f1; D = 8;  s = 16; N = 512;  n = idx - 4096; }
        else                 { fmap = f2; D = 4;  s = 32; N = 64;   n = idx - 4608; }

        float4* dst = (float4*)(g_fnorm + (size_t)gid * CCH);
        if (n >= N) {
            float4 z = make_float4(0.f, 0.f, 0.f, 0.f);
#pragma unroll
            for (int c = 0; c < CCH / 4; c++) dst[c] = z;
            g_cls[gid] = 3;
            return;
        }
        int z = n / (D * D), y = (n / D) % D, x = n % D;
        int tv = tgt[(size_t)b * VOX + ((size_t)(z * s) * 128 + y * s) * 128 + x * s];
        int cls = tv < 0 ? 0 : (tv > 2 ? 2 : tv);
        g_cls[gid] = cls;

        float v[CCH];
        float ss = 0.f;
#pragma unroll
        for (int c = 0; c < CCH; c++) {
            v[c] = fmap[((size_t)b * CCH + c) * N + n];
            ss = fmaf(v[c], v[c], ss);
        }
        float inv = 1.f / fmaxf(sqrtf(ss), 1e-12f);
#pragma unroll
        for (int c = 0; c < CCH / 4; c++)
            dst[c] = make_float4(v[4 * c] * inv, v[4 * c + 1] * inv,
                                 v[4 * c + 2] * inv, v[4 * c + 3] * inv);
    }
}

// ---------------- helpers ----------------
__device__ __forceinline__ void ffma2(unsigned long long& d,
                                      unsigned long long a,
                                      unsigned long long b) {
    asm("fma.rn.f32x2 %0, %1, %2, %0;" : "+l"(d) : "l"(a), "l"(b));
}
__device__ __forceinline__ float ex2f(float x) {
    float y;
    asm("ex2.approx.f32 %0, %1;" : "=f"(y) : "f"(x));
    return y;
}
__device__ double pair_loss(double S, double cnt, bool positive) {
    if (!(cnt > 0.0)) return 0.0;
    double mean = S / (cnt < 1.0 ? 1.0 : cnt);
    return positive ? -log(mean + 1e-6) : log1p(mean);
}

// ====== kernel B: gram (f32x2, 256 thr, 8x8) + ticketed finalize ======
#define BSTRIDE 50
__global__ void __launch_bounds__(256, 1)
gram_kernel(const float* __restrict__ logits,
            const int* __restrict__ labels,
            float* __restrict__ out) {
    int gid = blockIdx.x;
    int b, p, T, off;
    if (gid < 1056)      { b = gid / 528;  p = gid % 528; T = 32; off = 0; }
    else if (gid < 1076) { int l = gid - 1056; b = l / 10; p = l % 10; T = 4; off = 4096; }
    else                 { b = gid - 1076; p = 0; T = 1; off = 4608; }
    int by = 0;
    while (p >= T - by) { p -= T - by; by++; }
    int bx = by + p;

    extern __shared__ float sm[];
    float* As = sm;                          // [128][48]
    float* Bs = sm + 128 * 48;               // [128][BSTRIDE]
    float* wr = Bs + 128 * BSTRIDE;          // [3][128]
    float* wc = wr + 3 * 128;                // [3][128]

    int tid = threadIdx.x;
    const float4* FR4 = (const float4*)(g_fnorm + ((size_t)b * NPOS + off + by * 128) * CCH);
    const float2* FC2 = (const float2*)(g_fnorm + ((size_t)b * NPOS + off + bx * 128) * CCH);

    for (int t = tid; t < 128 * 12; t += 256)
        ((float4*)As)[t] = FR4[t];
    for (int t = tid; t < 128 * 24; t += 256) {      // 200B rows -> float2
        int r = t / 24, kq = t % 24;
        *(float2*)(Bs + r * BSTRIDE + kq * 2) = FC2[t];
    }
    if (tid < 128) {
        int cr = g_cls[b * NPOS + off + by * 128 + tid];
        wr[tid]       = (cr == 0) ? 1.f : 0.f;
        wr[128 + tid] = (cr == 1) ? 1.f : 0.f;
        wr[256 + tid] = (cr == 2) ? 1.f : 0.f;
    } else {
        int t2 = tid - 128;
        int cc = g_cls[b * NPOS + off + bx * 128 + t2];
        wc[t2]       = (cc == 0) ? 1.f : 0.f;
        wc[128 + t2] = (cc == 1) ? 1.f : 0.f;
        wc[256 + t2] = (cc == 2) ? 1.f : 0.f;
    }
    __syncthreads();

    int ty = tid >> 4, tx = tid & 15;
    // rows: ty*8 + i, cols: tx + j*16 ; BSTRIDE=50 -> banks tx*18 mod 32 distinct

    unsigned long long acc[8][8];
#pragma unroll
    for (int i = 0; i < 8; i++)
#pragma unroll
        for (int j = 0; j < 8; j++) acc[i][j] = 0ull;

#pragma unroll 1
    for (int k = 0; k < CCH; k += 2) {
        unsigned long long a2[8];
#pragma unroll
        for (int i = 0; i < 8; i++)
            a2[i] = *(const unsigned long long*)(As + (ty * 8 + i) * 48 + k);
#pragma unroll
        for (int j = 0; j < 8; j++) {
            unsigned long long b2 =
                *(const unsigned long long*)(Bs + (tx + j * 16) * BSTRIDE + k);
#pragma unroll
            for (int i = 0; i < 8; i++) ffma2(acc[i][j], a2[i], b2);
        }
    }

    float wc0[8], wc1[8], wc2[8];
#pragma unroll
    for (int j = 0; j < 8; j++) {
        int ml = tx + j * 16;
        wc0[j] = wc[ml];
        wc1[j] = wc[128 + ml];
        wc2[j] = wc[256 + ml];
    }

    float lacc[9];
#pragma unroll
    for (int q = 0; q < 9; q++) lacc[q] = 0.f;

    bool diag = (by == bx);
#pragma unroll
    for (int i = 0; i < 8; i++) {
        int rl = ty * 8 + i;
        float w0r = wr[rl], w1r = wr[128 + rl], w2r = wr[256 + rl];
        float rs0 = 0.f, rs1 = 0.f, rs2 = 0.f;
#pragma unroll
        for (int j = 0; j < 8; j++) {
            int ml = tx + j * 16;
            unsigned long long u = acc[i][j];
            float lo = __uint_as_float((unsigned)(u & 0xffffffffu));
            float hi = __uint_as_float((unsigned)(u >> 32));
            float E = ex2f((lo + hi) * 14.4269504088896340736f); // exp(dot/0.1)
            if (diag && ml <= rl) E = 0.f;                        // strict upper tri
            rs0 = fmaf(E, wc0[j], rs0);
            rs1 = fmaf(E, wc1[j], rs1);
            rs2 = fmaf(E, wc2[j], rs2);
        }
        lacc[0] = fmaf(w0r, rs0, lacc[0]);
        lacc[1] = fmaf(w0r, rs1, lacc[1]);
        lacc[2] = fmaf(w0r, rs2, lacc[2]);
        lacc[3] = fmaf(w1r, rs0, lacc[3]);
        lacc[4] = fmaf(w1r, rs1, lacc[4]);
        lacc[5] = fmaf(w1r, rs2, lacc[5]);
        lacc[6] = fmaf(w2r, rs0, lacc[6]);
        lacc[7] = fmaf(w2r, rs1, lacc[7]);
        lacc[8] = fmaf(w2r, rs2, lacc[8]);
    }

#pragma unroll
    for (int o = 16; o; o >>= 1)
#pragma unroll
        for (int q = 0; q < 9; q++)
            lacc[q] += __shfl_down_sync(0xffffffffu, lacc[q], o);

    __shared__ float rsum[8][9];
    int w = tid >> 5, l = tid & 31;
    if (l == 0)
#pragma unroll
        for (int q = 0; q < 9; q++) rsum[w][q] = lacc[q];
    __syncthreads();
    if (tid < 9) {
        float s = 0.f;
#pragma unroll
        for (int w2 = 0; w2 < 8; w2++) s += rsum[w2][tid];
        g_gpart[gid * 9 + tid] = s;
        __threadfence();                      // publish partial before ticket
    }
    __syncthreads();

    // ---- ticket: last block finalizes ----
    __shared__ unsigned int amLast;
    if (tid == 0) amLast = (atomicAdd(&g_ticket, 1u) == NGRAM - 1) ? 1u : 0u;
    __syncthreads();
    if (!amLast) return;

    // ================= finalize (one block, 256 threads) =================
    __shared__ double sred[256];
    __shared__ double sdice[2][9];
    __shared__ double sgp[6][9];
    __shared__ int    scnt[18];

    for (int bb = 0; bb < 2; bb++) {
        double a[9];
#pragma unroll
        for (int q = 0; q < 9; q++) a[q] = 0.0;
        for (int i = bb * 1024 + tid; i < (bb + 1) * 1024; i += 256)
#pragma unroll
            for (int q = 0; q < 9; q++) a[q] += (double)g_dpart[i * 9 + q];
        for (int q = 0; q < 9; q++) {
            sred[tid] = a[q];
            __syncthreads();
            for (int s = 128; s; s >>= 1) {
                if (tid < s) sred[tid] += sred[tid + s];
                __syncthreads();
            }
            if (tid == 0) sdice[bb][q] = sred[0];
            __syncthreads();
        }
    }

    if (tid < 32) {
        const int gs[7] = { 0, 528, 1056, 1066, 1076, 1077, 1078 };
        for (int g = 0; g < 6; g++) {
            double v[9];
#pragma unroll
            for (int q = 0; q < 9; q++) v[q] = 0.0;
            for (int i = gs[g] + tid; i < gs[g + 1]; i += 32)
#pragma unroll
                for (int q = 0; q < 9; q++) v[q] += (double)g_gpart[i * 9 + q];
#pragma unroll
            for (int q = 0; q < 9; q++)
                for (int o = 16; o; o >>= 1)
                    v[q] += __shfl_down_sync(0xffffffffu, v[q], o);
            if (tid == 0)
#pragma unroll
                for (int q = 0; q < 9; q++) sgp[g][q] = v[q];
        }
    } else if (tid < 64) {
        int ll = tid - 32;
        int c[18];
#pragma unroll
        for (int k = 0; k < 18; k++) c[k] = 0;
        for (int i = ll; i < 2 * NPOS; i += 32) {
            int cls = g_cls[i];
            if (cls > 2) continue;
            int bb = i / NPOS, idx = i % NPOS;
            int sc = idx < 4096 ? 0 : (idx < 4608 ? 1 : 2);
            c[(bb * 3 + sc) * 3 + cls]++;
        }
#pragma unroll
        for (int k = 0; k < 18; k++)
            for (int o = 16; o; o >>= 1)
                c[k] += __shfl_down_sync(0xffffffffu, c[k], o);
        if (ll == 0)
#pragma unroll
            for (int k = 0; k < 18; k++) scnt[k] = c[k];
    }
    __syncthreads();

    if (tid == 0) {
        double dsum = 0.0;
        for (int bb = 0; bb < 2; bb++)
            for (int c = 1; c < 3; c++) {
                double inter = sdice[bb][c];
                double psum  = sdice[bb][3 + c];
                double vcnt  = sdice[bb][6 + c];
                dsum += (2.0 * inter + 1e-5) / (psum + vcnt + 1e-5);
            }
        double dice = 1.0 - dsum / 4.0;

        double fsum = 0.0;
        for (int i = 0; i < 6; i++) {
            double x  = (double)logits[i];
            double pt = 1.0 / (1.0 + exp(-x));
            if (labels[i] != 1) pt = 1.0 - pt;
            double om = 1.0 - pt;
            fsum += -0.25 * om * om * log(pt + 1e-6);
        }
        double focal = fsum / 6.0;

        const double wsc[3] = { 1.0, 0.8, 0.6 };
        double contr = 0.0;
        for (int sc = 0; sc < 3; sc++) {
            double sl = 0.0;
            for (int bb = 0; bb < 2; bb++) {
                const double* Tt = sgp[sc * 2 + bb];
                const int* cc = scnt + (bb * 3 + sc) * 3;
                double c0 = cc[0], c1 = cc[1], c2 = cc[2];
                sl += pair_loss(2.0 * Tt[4],   c1 * c1 - c1, true);
                sl += pair_loss(2.0 * Tt[8],   c2 * c2 - c2, true);
                sl += pair_loss(Tt[5] + Tt[7], c1 * c2,      false);
                sl += pair_loss(Tt[1] + Tt[3], c0 * c1,      false);
                sl += pair_loss(Tt[2] + Tt[6], c0 * c2,      false);
            }
            contr += wsc[sc] * (sl * 0.5);
        }

        double total = dice + focal + 0.1 * contr;
        out[0] = (float)total;
        out[1] = (float)dice;
        out[2] = (float)focal;
        out[3] = (float)contr;
    }
}

// ================= launcher =================
extern "C" void kernel_launch(void* const* d_in, const int* in_sizes, int n_in,
                              void* d_out, int out_size) {
    const float* pred   = (const float*)d_in[0];
    const int*   tgt    = (const int*)d_in[1];
    const float* f0     = (const float*)d_in[2];
    const float* f1     = (const float*)d_in[3];
    const float* f2     = (const float*)d_in[4];
    const float* logits = (const float*)d_in[5];
    const int*   labels = (const int*)d_in[6];
    float*       out    = (float*)d_out;

    const int smemBytes = (128 * 48 + 128 * BSTRIDE + 6 * 128) * sizeof(float);
    cudaFuncSetAttribute(gram_kernel,
                         cudaFuncAttributeMaxDynamicSharedMemorySize, smemBytes);

    diceprep_kernel<<<NDICE + 37, 256>>>(pred, tgt, f0, f1, f2);
    gram_kernel<<<NGRAM, 256, smemBytes>>>(logits, labels, out);
}

// round 9
// speedup vs baseline: 1.0727x; 1.0727x over previous
#include <cuda_runtime.h>
#include <math.h>

// ---------------- constants ----------------
#define VOX   2097152          // 128^3
#define CCH   48               // feature channels
#define NPOS  4736             // 4096 + 512 + 128(pad) positions per batch
#define NGRAM 1078             // 2*528 + 2*10 + 2*1 gram tiles
#define NDICE 2048

// ---------------- device scratch ----------------
__device__ float g_dpart[NDICE * 9];      // dice per-block partials
__device__ float g_gpart[NGRAM * 9];      // gram per-block partials
__device__ float g_fnorm[2 * NPOS * CCH];
__device__ int   g_cls[2 * NPOS];
__device__ unsigned int g_ticket;

// ================= kernel A: fused dice + prep =================
__global__ void __launch_bounds__(256)
diceprep_kernel(const float* __restrict__ pred, const int* __restrict__ tgt,
                const float* __restrict__ f0, const float* __restrict__ f1,
                const float* __restrict__ f2) {
    int bid = blockIdx.x;
    if (bid == 0 && threadIdx.x == 0) g_ticket = 0;   // reset finalize ticket
    if (bid < NDICE) {
        const int b = bid >> 10;
        const int chunk = bid & 1023;
        const int Q = VOX / 4;
        float fi0 = 0.f, fi1 = 0.f, fi2 = 0.f;
        float fp0 = 0.f, fp1 = 0.f, fp2 = 0.f;
        float fc0 = 0.f, fc1 = 0.f, fc2 = 0.f;
        const float4* P  = (const float4*)pred;
        const int4*   T4 = (const int4*)tgt;

        for (int q = chunk * 256 + threadIdx.x; q < Q; q += 1024 * 256) {
            float4 x0 = P[(size_t)(b * 3 + 0) * Q + q];
            float4 x1 = P[(size_t)(b * 3 + 1) * Q + q];
            float4 x2 = P[(size_t)(b * 3 + 2) * Q + q];
            int4   tv = T4[(size_t)b * Q + q];

#define DO_VOXEL(pa, pb, pc, tt)                                           \
            {                                                              \
                float e0 = __expf(pa);                                     \
                float e1 = __expf(pb);                                     \
                float e2 = __expf(pc);                                     \
                float inv = __fdividef(1.f, e0 + e1 + e2);                 \
                e0 *= inv; e1 *= inv; e2 *= inv;                           \
                fp0 += e0; fp1 += e1; fp2 += e2;                           \
                int tc = (tt) < 0 ? 0 : (tt);                              \
                if (tc == 0)      { fi0 += e0; fc0 += 1.f; }               \
                else if (tc == 1) { fi1 += e1; fc1 += 1.f; }               \
                else              { fi2 += e2; fc2 += 1.f; }               \
            }
            DO_VOXEL(x0.x, x1.x, x2.x, tv.x);
            DO_VOXEL(x0.y, x1.y, x2.y, tv.y);
            DO_VOXEL(x0.z, x1.z, x2.z, tv.z);
            DO_VOXEL(x0.w, x1.w, x2.w, tv.w);
#undef DO_VOXEL
        }

        float v[9] = { fi0, fi1, fi2, fp0, fp1, fp2, fc0, fc1, fc2 };
#pragma unroll
        for (int o = 16; o; o >>= 1)
#pragma unroll
            for (int q = 0; q < 9; q++)
                v[q] += __shfl_down_sync(0xffffffffu, v[q], o);

        __shared__ float red[8][9];
        int w = threadIdx.x >> 5, l = threadIdx.x & 31;
        if (l == 0)
#pragma unroll
            for (int q = 0; q < 9; q++) red[w][q] = v[q];
        __syncthreads();
        if (threadIdx.x < 9) {
            float s = 0.f;
#pragma unroll
            for (int w2 = 0; w2 < 8; w2++) s += red[w2][threadIdx.x];
            g_dpart[bid * 9 + threadIdx.x] = s;
        }
    } else {
        int gid = (bid - NDICE) * 256 + threadIdx.x;
        if (gid >= 2 * NPOS) return;
        int b = gid / NPOS, idx = gid % NPOS;
        const float* fmap;
        int D, s, N, n;
        if (idx < 4096)      { fmap = f0; D = 16; s = 8;  N = 4096; n = idx; }
        else if (idx < 4608) { fmap = f1; D = 8;  s = 16; N = 512;  n = idx - 4096; }
        else                 { fmap = f2; D = 4;  s = 32; N = 64;   n = idx - 4608; }

        float4* dst = (float4*)(g_fnorm + (size_t)gid * CCH);
        if (n >= N) {
            float4 z = make_float4(0.f, 0.f, 0.f, 0.f);
#pragma unroll
            for (int c = 0; c < CCH / 4; c++) dst[c] = z;
            g_cls[gid] = 3;
            return;
        }
        int z = n / (D * D), y = (n / D) % D, x = n % D;
        int tv = tgt[(size_t)b * VOX + ((size_t)(z * s) * 128 + y * s) * 128 + x * s];
        int cls = tv < 0 ? 0 : (tv > 2 ? 2 : tv);
        g_cls[gid] = cls;

        float v[CCH];
        float ss = 0.f;
#pragma unroll
        for (int c = 0; c < CCH; c++) {
            v[c] = fmap[((size_t)b * CCH + c) * N + n];
            ss = fmaf(v[c], v[c], ss);
        }
        float inv = 1.f / fmaxf(sqrtf(ss), 1e-12f);
#pragma unroll
        for (int c = 0; c < CCH / 4; c++)
            dst[c] = make_float4(v[4 * c] * inv, v[4 * c + 1] * inv,
                                 v[4 * c + 2] * inv, v[4 * c + 3] * inv);
    }
}

// ---------------- helpers ----------------
__device__ __forceinline__ float ex2f(float x) {
    float y;
    asm("ex2.approx.f32 %0, %1;" : "=f"(y) : "f"(x));
    return y;
}
__device__ double pair_loss(double S, double cnt, bool positive) {
    if (!(cnt > 0.0)) return 0.0;
    double mean = S / (cnt < 1.0 ? 1.0 : cnt);
    return positive ? -log(mean + 1e-6) : log1p(mean);
}

// ====== kernel B: gram scalar-FFMA, 2 CTAs/SM forced, + ticketed finalize ===
#define BSTRIDE 52
__global__ void __launch_bounds__(256, 2)
gram_kernel(const float* __restrict__ logits,
            const int* __restrict__ labels,
            float* __restrict__ out) {
    int gid = blockIdx.x;
    int b, p, T, off;
    if (gid < 1056)      { b = gid / 528;  p = gid % 528; T = 32; off = 0; }
    else if (gid < 1076) { int l = gid - 1056; b = l / 10; p = l % 10; T = 4; off = 4096; }
    else                 { b = gid - 1076; p = 0; T = 1; off = 4608; }
    int by = 0;
    while (p >= T - by) { p -= T - by; by++; }
    int bx = by + p;

    extern __shared__ float sm[];
    float* As = sm;                          // [128][48]
    float* Bs = sm + 128 * 48;               // [128][BSTRIDE]
    float* wr = Bs + 128 * BSTRIDE;          // [3][128]
    float* wc = wr + 3 * 128;                // [3][128]

    int tid = threadIdx.x;
    const float4* FR4 = (const float4*)(g_fnorm + ((size_t)b * NPOS + off + by * 128) * CCH);
    const float4* FC4 = (const float4*)(g_fnorm + ((size_t)b * NPOS + off + bx * 128) * CCH);

    for (int t = tid; t < 128 * 12; t += 256)
        ((float4*)As)[t] = FR4[t];
    for (int t = tid; t < 128 * 12; t += 256) {
        int r = t / 12, kq = t % 12;
        *(float4*)(Bs + r * BSTRIDE + kq * 4) = FC4[t];   // 52%4==0 -> aligned
    }
    if (tid < 128) {
        int cr = g_cls[b * NPOS + off + by * 128 + tid];
        wr[tid]       = (cr == 0) ? 1.f : 0.f;
        wr[128 + tid] = (cr == 1) ? 1.f : 0.f;
        wr[256 + tid] = (cr == 2) ? 1.f : 0.f;
    } else {
        int t2 = tid - 128;
        int cc = g_cls[b * NPOS + off + bx * 128 + t2];
        wc[t2]       = (cc == 0) ? 1.f : 0.f;
        wc[128 + t2] = (cc == 1) ? 1.f : 0.f;
        wc[256 + t2] = (cc == 2) ? 1.f : 0.f;
    }
    __syncthreads();

    int ty = tid >> 4, tx = tid & 15;
    // rows: ty*8 + i, cols: tx + j*16
    // LDS.128 banks: a = intra-phase broadcast; b = tx*20 mod 32 distinct

    float acc[8][8];
#pragma unroll
    for (int i = 0; i < 8; i++)
#pragma unroll
        for (int j = 0; j < 8; j++) acc[i][j] = 0.f;

#pragma unroll 1
    for (int kc = 0; kc < 12; kc++) {
        float4 a4[8];
#pragma unroll
        for (int i = 0; i < 8; i++)
            a4[i] = *(const float4*)(As + (ty * 8 + i) * 48 + kc * 4);
#pragma unroll
        for (int j = 0; j < 8; j++) {
            float4 b4 = *(const float4*)(Bs + (tx + j * 16) * BSTRIDE + kc * 4);
#pragma unroll
            for (int i = 0; i < 8; i++) {
                acc[i][j] = fmaf(a4[i].x, b4.x, acc[i][j]);
                acc[i][j] = fmaf(a4[i].y, b4.y, acc[i][j]);
                acc[i][j] = fmaf(a4[i].z, b4.z, acc[i][j]);
                acc[i][j] = fmaf(a4[i].w, b4.w, acc[i][j]);
            }
        }
    }

    float lacc[9];
#pragma unroll
    for (int q = 0; q < 9; q++) lacc[q] = 0.f;

    bool diag = (by == bx);
#pragma unroll
    for (int i = 0; i < 8; i++) {
        int rl = ty * 8 + i;
        float w0r = wr[rl], w1r = wr[128 + rl], w2r = wr[256 + rl];
        float rs0 = 0.f, rs1 = 0.f, rs2 = 0.f;
#pragma unroll
        for (int j = 0; j < 8; j++) {
            int ml = tx + j * 16;
            float E = ex2f(acc[i][j] * 14.4269504088896340736f); // exp(dot/0.1)
            if (diag && ml <= rl) E = 0.f;                        // strict upper tri
            rs0 = fmaf(E, wc[ml],       rs0);
            rs1 = fmaf(E, wc[128 + ml], rs1);
            rs2 = fmaf(E, wc[256 + ml], rs2);
        }
        lacc[0] = fmaf(w0r, rs0, lacc[0]);
        lacc[1] = fmaf(w0r, rs1, lacc[1]);
        lacc[2] = fmaf(w0r, rs2, lacc[2]);
        lacc[3] = fmaf(w1r, rs0, lacc[3]);
        lacc[4] = fmaf(w1r, rs1, lacc[4]);
        lacc[5] = fmaf(w1r, rs2, lacc[5]);
        lacc[6] = fmaf(w2r, rs0, lacc[6]);
        lacc[7] = fmaf(w2r, rs1, lacc[7]);
        lacc[8] = fmaf(w2r, rs2, lacc[8]);
    }

#pragma unroll
    for (int o = 16; o; o >>= 1)
#pragma unroll
        for (int q = 0; q < 9; q++)
            lacc[q] += __shfl_down_sync(0xffffffffu, lacc[q], o);

    __shared__ float rsum[8][9];
    int w = tid >> 5, l = tid & 31;
    if (l == 0)
#pragma unroll
        for (int q = 0; q < 9; q++) rsum[w][q] = lacc[q];
    __syncthreads();
    if (tid < 9) {
        float s = 0.f;
#pragma unroll
        for (int w2 = 0; w2 < 8; w2++) s += rsum[w2][tid];
        g_gpart[gid * 9 + tid] = s;
        __threadfence();                      // publish partial before ticket
    }
    __syncthreads();

    // ---- ticket: last block finalizes ----
    __shared__ unsigned int amLast;
    if (tid == 0) amLast = (atomicAdd(&g_ticket, 1u) == NGRAM - 1) ? 1u : 0u;
    __syncthreads();
    if (!amLast) return;

    // ================= finalize (one block, 256 threads) =================
    __shared__ double sred[256];
    __shared__ double sdice[2][9];
    __shared__ double sgp[6][9];
    __shared__ int    scnt[18];

    for (int bb = 0; bb < 2; bb++) {
        double a[9];
#pragma unroll
        for (int q = 0; q < 9; q++) a[q] = 0.0;
        for (int i = bb * 1024 + tid; i < (bb + 1) * 1024; i += 256)
#pragma unroll
            for (int q = 0; q < 9; q++) a[q] += (double)g_dpart[i * 9 + q];
        for (int q = 0; q < 9; q++) {
            sred[tid] = a[q];
            __syncthreads();
            for (int s = 128; s; s >>= 1) {
                if (tid < s) sred[tid] += sred[tid + s];
                __syncthreads();
            }
            if (tid == 0) sdice[bb][q] = sred[0];
            __syncthreads();
        }
    }

    if (tid < 32) {
        const int gs[7] = { 0, 528, 1056, 1066, 1076, 1077, 1078 };
        for (int g = 0; g < 6; g++) {
            double v[9];
#pragma unroll
            for (int q = 0; q < 9; q++) v[q] = 0.0;
            for (int i = gs[g] + tid; i < gs[g + 1]; i += 32)
#pragma unroll
                for (int q = 0; q < 9; q++) v[q] += (double)g_gpart[i * 9 + q];
#pragma unroll
            for (int q = 0; q < 9; q++)
                for (int o = 16; o; o >>= 1)
                    v[q] += __shfl_down_sync(0xffffffffu, v[q], o);
            if (tid == 0)
#pragma unroll
                for (int q = 0; q < 9; q++) sgp[g][q] = v[q];
        }
    } else if (tid < 64) {
        int ll = tid - 32;
        int c[18];
#pragma unroll
        for (int k = 0; k < 18; k++) c[k] = 0;
        for (int i = ll; i < 2 * NPOS; i += 32) {
            int cls = g_cls[i];
            if (cls > 2) continue;
            int bb = i / NPOS, idx = i % NPOS;
            int sc = idx < 4096 ? 0 : (idx < 4608 ? 1 : 2);
            c[(bb * 3 + sc) * 3 + cls]++;
        }
#pragma unroll
        for (int k = 0; k < 18; k++)
            for (int o = 16; o; o >>= 1)
                c[k] += __shfl_down_sync(0xffffffffu, c[k], o);
        if (ll == 0)
#pragma unroll
            for (int k = 0; k < 18; k++) scnt[k] = c[k];
    }
    __syncthreads();

    if (tid == 0) {
        double dsum = 0.0;
        for (int bb = 0; bb < 2; bb++)
            for (int c = 1; c < 3; c++) {
                double inter = sdice[bb][c];
                double psum  = sdice[bb][3 + c];
                double vcnt  = sdice[bb][6 + c];
                dsum += (2.0 * inter + 1e-5) / (psum + vcnt + 1e-5);
            }
        double dice = 1.0 - dsum / 4.0;

        double fsum = 0.0;
        for (int i = 0; i < 6; i++) {
            double x  = (double)logits[i];
            double pt = 1.0 / (1.0 + exp(-x));
            if (labels[i] != 1) pt = 1.0 - pt;
            double om = 1.0 - pt;
            fsum += -0.25 * om * om * log(pt + 1e-6);
        }
        double focal = fsum / 6.0;

        const double wsc[3] = { 1.0, 0.8, 0.6 };
        double contr = 0.0;
        for (int sc = 0; sc < 3; sc++) {
            double sl = 0.0;
            for (int bb = 0; bb < 2; bb++) {
                const double* Tt = sgp[sc * 2 + bb];
                const int* cc = scnt + (bb * 3 + sc) * 3;
                double c0 = cc[0], c1 = cc[1], c2 = cc[2];
                sl += pair_loss(2.0 * Tt[4],   c1 * c1 - c1, true);
                sl += pair_loss(2.0 * Tt[8],   c2 * c2 - c2, true);
                sl += pair_loss(Tt[5] + Tt[7], c1 * c2,      false);
                sl += pair_loss(Tt[1] + Tt[3], c0 * c1,      false);
                sl += pair_loss(Tt[2] + Tt[6], c0 * c2,      false);
            }
            contr += wsc[sc] * (sl * 0.5);
        }

        double total = dice + focal + 0.1 * contr;
        out[0] = (float)total;
        out[1] = (float)dice;
        out[2] = (float)focal;
        out[3] = (float)contr;
    }
}

// ================= launcher =================
extern "C" void kernel_launch(void* const* d_in, const int* in_sizes, int n_in,
                              void* d_out, int out_size) {
    const float* pred   = (const float*)d_in[0];
    const int*   tgt    = (const int*)d_in[1];
    const float* f0     = (const float*)d_in[2];
    const float* f1     = (const float*)d_in[3];
    const float* f2     = (const float*)d_in[4];
    const float* logits = (const float*)d_in[5];
    const int*   labels = (const int*)d_in[6];
    float*       out    = (float*)d_out;

    const int smemBytes = (128 * 48 + 128 * BSTRIDE + 6 * 128) * sizeof(float);
    cudaFuncSetAttribute(gram_kernel,
                         cudaFuncAttributeMaxDynamicSharedMemorySize, smemBytes);

    diceprep_kernel<<<NDICE + 37, 256>>>(pred, tgt, f0, f1, f2);
    gram_kernel<<<NGRAM, 256, smemBytes>>>(logits, labels, out);
}

// round 12
// speedup vs baseline: 1.3037x; 1.2153x over previous
#include <cuda_runtime.h>
#include <cuda_bf16.h>
#include <math.h>
#include <cstdint>

// ---------------- constants ----------------
#define VOX   2097152
#define CCH   48
#define PADK  104                // [hi 48 | lo 48 | pad 8] bf16 -> 208B rows
#define KEXT  96                 // MMA K extent (hi+lo)
#define NPOS  4736               // 4096 + 512 + 128(pad)
#define NGRAM 1078
#define NDICE 2048

// ---------------- device scratch ----------------
__device__ float g_dpart[NDICE * 9];
__device__ float g_gpart[NGRAM * 9];
__device__ __align__(16) __nv_bfloat16 g_f[2 * NPOS * PADK];
__device__ int   g_cls[2 * NPOS];
__device__ unsigned int g_ticket;

// ================= kernel A: fused dice + prep =================
__global__ void __launch_bounds__(256)
diceprep_kernel(const float* __restrict__ pred, const int* __restrict__ tgt,
                const float* __restrict__ f0, const float* __restrict__ f1,
                const float* __restrict__ f2) {
    int bid = blockIdx.x;
    if (bid == 0 && threadIdx.x == 0) g_ticket = 0;
    if (bid < NDICE) {
        const int b = bid >> 10;
        const int chunk = bid & 1023;
        const int Q = VOX / 4;
        float fi0 = 0.f, fi1 = 0.f, fi2 = 0.f;
        float fp0 = 0.f, fp1 = 0.f, fp2 = 0.f;
        float fc0 = 0.f, fc1 = 0.f, fc2 = 0.f;
        const float4* P  = (const float4*)pred;
        const int4*   T4 = (const int4*)tgt;

        for (int q = chunk * 256 + threadIdx.x; q < Q; q += 1024 * 256) {
            float4 x0 = P[(size_t)(b * 3 + 0) * Q + q];
            float4 x1 = P[(size_t)(b * 3 + 1) * Q + q];
            float4 x2 = P[(size_t)(b * 3 + 2) * Q + q];
            int4   tv = T4[(size_t)b * Q + q];

#define DO_VOXEL(pa, pb, pc, tt)                                           \
            {                                                              \
                float e1 = __expf((pb) - (pa));                            \
                float e2 = __expf((pc) - (pa));                            \
                float inv = __fdividef(1.f, 1.f + e1 + e2);                \
                float p0 = inv, p1 = e1 * inv, p2 = e2 * inv;              \
                fp0 += p0; fp1 += p1; fp2 += p2;                           \
                int tc = (tt) < 0 ? 0 : (tt);                              \
                if (tc == 0)      { fi0 += p0; fc0 += 1.f; }               \
                else if (tc == 1) { fi1 += p1; fc1 += 1.f; }               \
                else              { fi2 += p2; fc2 += 1.f; }               \
            }
            DO_VOXEL(x0.x, x1.x, x2.x, tv.x);
            DO_VOXEL(x0.y, x1.y, x2.y, tv.y);
            DO_VOXEL(x0.z, x1.z, x2.z, tv.z);
            DO_VOXEL(x0.w, x1.w, x2.w, tv.w);
#undef DO_VOXEL
        }

        float v[9] = { fi0, fi1, fi2, fp0, fp1, fp2, fc0, fc1, fc2 };
#pragma unroll
        for (int o = 16; o; o >>= 1)
#pragma unroll
            for (int q = 0; q < 9; q++)
                v[q] += __shfl_down_sync(0xffffffffu, v[q], o);

        __shared__ float red[8][9];
        int w = threadIdx.x >> 5, l = threadIdx.x & 31;
        if (l == 0)
#pragma unroll
            for (int q = 0; q < 9; q++) red[w][q] = v[q];
        __syncthreads();
        if (threadIdx.x < 9) {
            float s = 0.f;
#pragma unroll
            for (int w2 = 0; w2 < 8; w2++) s += red[w2][threadIdx.x];
            g_dpart[bid * 9 + threadIdx.x] = s;
        }
    } else {
        int gid = (bid - NDICE) * 256 + threadIdx.x;
        if (gid >= 2 * NPOS) return;
        int b = gid / NPOS, idx = gid % NPOS;
        const float* fmap;
        int D, s, N, n;
        if (idx < 4096)      { fmap = f0; D = 16; s = 8;  N = 4096; n = idx; }
        else if (idx < 4608) { fmap = f1; D = 8;  s = 16; N = 512;  n = idx - 4096; }
        else                 { fmap = f2; D = 4;  s = 32; N = 64;   n = idx - 4608; }

        __nv_bfloat16* dst = g_f + (size_t)gid * PADK;
        if (n >= N) {
            for (int c = 0; c < PADK; c++) dst[c] = __float2bfloat16(0.f);
            g_cls[gid] = 3;
            return;
        }
        int z = n / (D * D), y = (n / D) % D, x = n % D;
        int tv = tgt[(size_t)b * VOX + ((size_t)(z * s) * 128 + y * s) * 128 + x * s];
        int cls = tv < 0 ? 0 : (tv > 2 ? 2 : tv);
        g_cls[gid] = cls;

        float v[CCH];
        float ss = 0.f;
#pragma unroll
        for (int c = 0; c < CCH; c++) {
            v[c] = fmap[((size_t)b * CCH + c) * N + n];
            ss = fmaf(v[c], v[c], ss);
        }
        float inv = 1.f / fmaxf(sqrtf(ss), 1e-12f);
#pragma unroll
        for (int c = 0; c < CCH; c++) {
            float f = v[c] * inv;
            __nv_bfloat16 h = __float2bfloat16(f);
            dst[c]       = h;                                        // hi
            dst[48 + c]  = __float2bfloat16(f - __bfloat162float(h)); // lo
        }
        for (int c = KEXT; c < PADK; c++) dst[c] = __float2bfloat16(0.f);
    }
}

// ---------------- helpers ----------------
__device__ __forceinline__ float ex2f(float x) {
    float y;
    asm("ex2.approx.f32 %0, %1;" : "=f"(y) : "f"(x));
    return y;
}
__device__ __forceinline__ void mma16816(float* c, const uint32_t* a, const uint32_t* b) {
    asm volatile(
        "mma.sync.aligned.m16n8k16.row.col.f32.bf16.bf16.f32 "
        "{%0,%1,%2,%3}, {%4,%5,%6,%7}, {%8,%9}, {%0,%1,%2,%3};"
        : "+f"(c[0]), "+f"(c[1]), "+f"(c[2]), "+f"(c[3])
        : "r"(a[0]), "r"(a[1]), "r"(a[2]), "r"(a[3]), "r"(b[0]), "r"(b[1]));
}
__device__ double pair_loss(double S, double cnt, bool positive) {
    if (!(cnt > 0.0)) return 0.0;
    double mean = S / (cnt < 1.0 ? 1.0 : cnt);
    return positive ? -log(mean + 1e-6) : log1p(mean);
}

// ====== kernel B: HMMA gram (hi/lo bf16, K=96) + ticketed finalize ======
__global__ void __launch_bounds__(256, 2)
gram_kernel(const float* __restrict__ logits,
            const int* __restrict__ labels,
            float* __restrict__ out) {
    int gid = blockIdx.x;
    int b, p, T, off;
    if (gid < 1056)      { b = gid / 528;  p = gid % 528; T = 32; off = 0; }
    else if (gid < 1076) { int l2 = gid - 1056; b = l2 / 10; p = l2 % 10; T = 4; off = 4096; }
    else                 { b = gid - 1076; p = 0; T = 1; off = 4608; }
    int by = 0;
    while (p >= T - by) { p -= T - by; by++; }
    int bx = by + p;

    extern __shared__ char smc[];
    __nv_bfloat16* As = (__nv_bfloat16*)smc;                  // [128][PADK]
    __nv_bfloat16* Bs = (__nv_bfloat16*)(smc + 128 * PADK * 2);
    float* wr = (float*)(smc + 2 * 128 * PADK * 2);           // [3][128]
    float* wc = wr + 3 * 128;

    int tid = threadIdx.x, wid = tid >> 5, lane = tid & 31;

    const uint4* GA = (const uint4*)(g_f + (size_t)(b * NPOS + off + by * 128) * PADK);
    const uint4* GB = (const uint4*)(g_f + (size_t)(b * NPOS + off + bx * 128) * PADK);
    // 128 rows x 208B = 1664 uint4 per tile, identical layout -> straight copy
    for (int t = tid; t < 1664; t += 256) {
        ((uint4*)As)[t] = GA[t];
        ((uint4*)Bs)[t] = GB[t];
    }
    if (tid < 128) {
        int cr = g_cls[b * NPOS + off + by * 128 + tid];
        wr[tid]       = (cr == 0) ? 1.f : 0.f;
        wr[128 + tid] = (cr == 1) ? 1.f : 0.f;
        wr[256 + tid] = (cr == 2) ? 1.f : 0.f;
    } else {
        int t2 = tid - 128;
        int cc = g_cls[b * NPOS + off + bx * 128 + t2];
        wc[t2]       = (cc == 0) ? 1.f : 0.f;
        wc[128 + t2] = (cc == 1) ? 1.f : 0.f;
        wc[256 + t2] = (cc == 2) ? 1.f : 0.f;
    }
    __syncthreads();

    // 8 warps: warp_m = wid & 3 (32 rows each), warp_n = wid >> 2 (64 cols each)
    int warp_m = wid & 3, warp_n = wid >> 2;
    int qr = lane >> 2, qc = lane & 3;   // fragment coords

    float acc[2][8][4];
#pragma unroll
    for (int mt = 0; mt < 2; mt++)
#pragma unroll
        for (int nt = 0; nt < 8; nt++)
#pragma unroll
            for (int e = 0; e < 4; e++) acc[mt][nt][e] = 0.f;

#pragma unroll
    for (int ks = 0; ks < 6; ks++) {
        int k0 = ks * 16 + qc * 2;
        uint32_t afr[2][4];
#pragma unroll
        for (int mt = 0; mt < 2; mt++) {
            int r = warp_m * 32 + mt * 16 + qr;
            afr[mt][0] = *(const uint32_t*)(As + r * PADK + k0);
            afr[mt][1] = *(const uint32_t*)(As + (r + 8) * PADK + k0);
            afr[mt][2] = *(const uint32_t*)(As + r * PADK + k0 + 8);
            afr[mt][3] = *(const uint32_t*)(As + (r + 8) * PADK + k0 + 8);
        }
#pragma unroll
        for (int nt = 0; nt < 8; nt++) {
            int n = warp_n * 64 + nt * 8 + qr;
            uint32_t bfr[2];
            bfr[0] = *(const uint32_t*)(Bs + n * PADK + k0);
            bfr[1] = *(const uint32_t*)(Bs + n * PADK + k0 + 8);
            mma16816(acc[0][nt], afr[0], bfr);
            mma16816(acc[1][nt], afr[1], bfr);
        }
    }

    // ---- epilogue: exp + one-hot class-pair sums ----
    const float L2E10 = 14.4269504088896340736f;   // 10 * log2(e)
    bool diag = (by == bx);
    float lacc[9];
#pragma unroll
    for (int q = 0; q < 9; q++) lacc[q] = 0.f;

#pragma unroll
    for (int mt = 0; mt < 2; mt++) {
        int r0 = warp_m * 32 + mt * 16 + qr;
        int r1 = r0 + 8;
        float wA0 = wr[r0], wA1 = wr[128 + r0], wA2 = wr[256 + r0];
        float wB0 = wr[r1], wB1 = wr[128 + r1], wB2 = wr[256 + r1];
        float ra0 = 0.f, ra1 = 0.f, ra2 = 0.f;   // row r0 sums by col class
        float rb0 = 0.f, rb1 = 0.f, rb2 = 0.f;   // row r1
#pragma unroll
        for (int nt = 0; nt < 8; nt++) {
            int c0 = warp_n * 64 + nt * 8 + qc * 2;
            int c1 = c0 + 1;
            float u00 = wc[c0], u01 = wc[128 + c0], u02 = wc[256 + c0];
            float u10 = wc[c1], u11 = wc[128 + c1], u12 = wc[256 + c1];
            float E00 = ex2f(acc[mt][nt][0] * L2E10);
            float E01 = ex2f(acc[mt][nt][1] * L2E10);
            float E10 = ex2f(acc[mt][nt][2] * L2E10);
            float E11 = ex2f(acc[mt][nt][3] * L2E10);
            if (diag) {
                if (c0 <= r0) E00 = 0.f;
                if (c1 <= r0) E01 = 0.f;
                if (c0 <= r1) E10 = 0.f;
                if (c1 <= r1) E11 = 0.f;
            }
            ra0 = fmaf(E00, u00, fmaf(E01, u10, ra0));
            ra1 = fmaf(E00, u01, fmaf(E01, u11, ra1));
            ra2 = fmaf(E00, u02, fmaf(E01, u12, ra2));
            rb0 = fmaf(E10, u00, fmaf(E11, u10, rb0));
            rb1 = fmaf(E10, u01, fmaf(E11, u11, rb1));
            rb2 = fmaf(E10, u02, fmaf(E11, u12, rb2));
        }
        lacc[0] = fmaf(wA0, ra0, fmaf(wB0, rb0, lacc[0]));
        lacc[1] = fmaf(wA0, ra1, fmaf(wB0, rb1, lacc[1]));
        lacc[2] = fmaf(wA0, ra2, fmaf(wB0, rb2, lacc[2]));
        lacc[3] = fmaf(wA1, ra0, fmaf(wB1, rb0, lacc[3]));
        lacc[4] = fmaf(wA1, ra1, fmaf(wB1, rb1, lacc[4]));
        lacc[5] = fmaf(wA1, ra2, fmaf(wB1, rb2, lacc[5]));
        lacc[6] = fmaf(wA2, ra0, fmaf(wB2, rb0, lacc[6]));
        lacc[7] = fmaf(wA2, ra1, fmaf(wB2, rb1, lacc[7]));
        lacc[8] = fmaf(wA2, ra2, fmaf(wB2, rb2, lacc[8]));
    }

#pragma unroll
    for (int o = 16; o; o >>= 1)
#pragma unroll
        for (int q = 0; q < 9; q++)
            lacc[q] += __shfl_down_sync(0xffffffffu, lacc[q], o);

    __shared__ float rsum[8][9];
    if (lane == 0)
#pragma unroll
        for (int q = 0; q < 9; q++) rsum[wid][q] = lacc[q];
    __syncthreads();
    if (tid < 9) {
        float s = 0.f;
#pragma unroll
        for (int w2 = 0; w2 < 8; w2++) s += rsum[w2][tid];
        g_gpart[gid * 9 + tid] = s;
        __threadfence();
    }
    __syncthreads();

    __shared__ unsigned int amLast;
    if (tid == 0) amLast = (atomicAdd(&g_ticket, 1u) == NGRAM - 1) ? 1u : 0u;
    __syncthreads();
    if (!amLast) return;

    // ================= finalize (one block, 256 threads) =================
    __shared__ double sred[256];
    __shared__ double sdice[2][9];
    __shared__ double sgp[6][9];
    __shared__ int    scnt[18];

    for (int bb = 0; bb < 2; bb++) {
        double a[9];
#pragma unroll
        for (int q = 0; q < 9; q++) a[q] = 0.0;
        for (int i = bb * 1024 + tid; i < (bb + 1) * 1024; i += 256)
#pragma unroll
            for (int q = 0; q < 9; q++) a[q] += (double)g_dpart[i * 9 + q];
        for (int q = 0; q < 9; q++) {
            sred[tid] = a[q];
            __syncthreads();
            for (int s = 128; s; s >>= 1) {
                if (tid < s) sred[tid] += sred[tid + s];
                __syncthreads();
            }
            if (tid == 0) sdice[bb][q] = sred[0];
            __syncthreads();
        }
    }

    if (tid < 32) {
        const int gs[7] = { 0, 528, 1056, 1066, 1076, 1077, 1078 };
        for (int g = 0; g < 6; g++) {
            double v[9];
#pragma unroll
            for (int q = 0; q < 9; q++) v[q] = 0.0;
            for (int i = gs[g] + tid; i < gs[g + 1]; i += 32)
#pragma unroll
                for (int q = 0; q < 9; q++) v[q] += (double)g_gpart[i * 9 + q];
#pragma unroll
            for (int q = 0; q < 9; q++)
                for (int o = 16; o; o >>= 1)
                    v[q] += __shfl_down_sync(0xffffffffu, v[q], o);
            if (tid == 0)
#pragma unroll
                for (int q = 0; q < 9; q++) sgp[g][q] = v[q];
        }
    } else if (tid < 64) {
        int ll = tid - 32;
        int c[18];
#pragma unroll
        for (int k = 0; k < 18; k++) c[k] = 0;
        for (int i = ll; i < 2 * NPOS; i += 32) {
            int cls = g_cls[i];
            if (cls > 2) continue;
            int bb = i / NPOS, idx = i % NPOS;
            int sc = idx < 4096 ? 0 : (idx < 4608 ? 1 : 2);
            c[(bb * 3 + sc) * 3 + cls]++;
        }
#pragma unroll
        for (int k = 0; k < 18; k++)
            for (int o = 16; o; o >>= 1)
                c[k] += __shfl_down_sync(0xffffffffu, c[k], o);
        if (ll == 0)
#pragma unroll
            for (int k = 0; k < 18; k++) scnt[k] = c[k];
    }
    __syncthreads();

    if (tid == 0) {
        double dsum = 0.0;
        for (int bb = 0; bb < 2; bb++)
            for (int c = 1; c < 3; c++) {
                double inter = sdice[bb][c];
                double psum  = sdice[bb][3 + c];
                double vcnt  = sdice[bb][6 + c];
                dsum += (2.0 * inter + 1e-5) / (psum + vcnt + 1e-5);
            }
        double dice = 1.0 - dsum / 4.0;

        double fsum = 0.0;
        for (int i = 0; i < 6; i++) {
            double x  = (double)logits[i];
            double pt = 1.0 / (1.0 + exp(-x));
            if (labels[i] != 1) pt = 1.0 - pt;
            double om = 1.0 - pt;
            fsum += -0.25 * om * om * log(pt + 1e-6);
        }
        double focal = fsum / 6.0;

        const double wsc[3] = { 1.0, 0.8, 0.6 };
        double contr = 0.0;
        for (int sc = 0; sc < 3; sc++) {
            double sl = 0.0;
            for (int bb = 0; bb < 2; bb++) {
                const double* Tt = sgp[sc * 2 + bb];
                const int* cc = scnt + (bb * 3 + sc) * 3;
                double c0 = cc[0], c1 = cc[1], c2 = cc[2];
                sl += pair_loss(2.0 * Tt[4],   c1 * c1 - c1, true);
                sl += pair_loss(2.0 * Tt[8],   c2 * c2 - c2, true);
                sl += pair_loss(Tt[5] + Tt[7], c1 * c2,      false);
                sl += pair_loss(Tt[1] + Tt[3], c0 * c1,      false);
                sl += pair_loss(Tt[2] + Tt[6], c0 * c2,      false);
            }
            contr += wsc[sc] * (sl * 0.5);
        }

        double total = dice + focal + 0.1 * contr;
        out[0] = (float)total;
        out[1] = (float)dice;
        out[2] = (float)focal;
        out[3] = (float)contr;
    }
}

// ================= launcher =================
extern "C" void kernel_launch(void* const* d_in, const int* in_sizes, int n_in,
                              void* d_out, int out_size) {
    const float* pred   = (const float*)d_in[0];
    const int*   tgt    = (const int*)d_in[1];
    const float* f0     = (const float*)d_in[2];
    const float* f1     = (const float*)d_in[3];
    const float* f2     = (const float*)d_in[4];
    const float* logits = (const float*)d_in[5];
    const int*   labels = (const int*)d_in[6];
    float*       out    = (float*)d_out;

    const int smemBytes = 2 * 128 * PADK * 2 + 6 * 128 * 4;   // 53248 + 3072
    cudaFuncSetAttribute(gram_kernel,
                         cudaFuncAttributeMaxDynamicSharedMemorySize, smemBytes);

    diceprep_kernel<<<NDICE + 37, 256>>>(pred, tgt, f0, f1, f2);
    gram_kernel<<<NGRAM, 256, smemBytes>>>(logits, labels, out);
}

// round 13
// speedup vs baseline: 1.9117x; 1.4664x over previous
#include <cuda_runtime.h>
#include <cuda_bf16.h>
#include <math.h>
#include <cstdint>

// ---------------- constants ----------------
#define VOX   2097152
#define CCH   48
#define PADK  104                // [hi 48 | lo 48 | pad 8] bf16 -> 208B rows
#define KEXT  96                 // MMA K extent (hi+lo)
#define NPOS  4736               // 4096 + 512 + 128(pad)
#define NGRAM 1078
#define NDICE 2048

// ---------------- device scratch ----------------
__device__ float g_dpart[NDICE * 9];
__device__ float g_gpart[NGRAM * 9];
__device__ __align__(16) __nv_bfloat16 g_f[2 * NPOS * PADK];
__device__ int   g_cls[2 * NPOS];
__device__ unsigned int g_ticket;

// ================= kernel A: fused dice + prep =================
__global__ void __launch_bounds__(256)
diceprep_kernel(const float* __restrict__ pred, const int* __restrict__ tgt,
                const float* __restrict__ f0, const float* __restrict__ f1,
                const float* __restrict__ f2) {
    int bid = blockIdx.x;
    if (bid == 0 && threadIdx.x == 0) g_ticket = 0;
    if (bid < NDICE) {
        const int b = bid >> 10;
        const int chunk = bid & 1023;
        const int Q = VOX / 4;
        float fi0 = 0.f, fi1 = 0.f, fi2 = 0.f;
        float fp0 = 0.f, fp1 = 0.f, fp2 = 0.f;
        float fc0 = 0.f, fc1 = 0.f, fc2 = 0.f;
        const float4* P  = (const float4*)pred;
        const int4*   T4 = (const int4*)tgt;

        for (int q = chunk * 256 + threadIdx.x; q < Q; q += 1024 * 256) {
            float4 x0 = P[(size_t)(b * 3 + 0) * Q + q];
            float4 x1 = P[(size_t)(b * 3 + 1) * Q + q];
            float4 x2 = P[(size_t)(b * 3 + 2) * Q + q];
            int4   tv = T4[(size_t)b * Q + q];

#define DO_VOXEL(pa, pb, pc, tt)                                           \
            {                                                              \
                float e1 = __expf((pb) - (pa));                            \
                float e2 = __expf((pc) - (pa));                            \
                float inv = __fdividef(1.f, 1.f + e1 + e2);                \
                float p0 = inv, p1 = e1 * inv, p2 = e2 * inv;              \
                fp0 += p0; fp1 += p1; fp2 += p2;                           \
                int tc = (tt) < 0 ? 0 : (tt);                              \
                if (tc == 0)      { fi0 += p0; fc0 += 1.f; }               \
                else if (tc == 1) { fi1 += p1; fc1 += 1.f; }               \
                else              { fi2 += p2; fc2 += 1.f; }               \
            }
            DO_VOXEL(x0.x, x1.x, x2.x, tv.x);
            DO_VOXEL(x0.y, x1.y, x2.y, tv.y);
            DO_VOXEL(x0.z, x1.z, x2.z, tv.z);
            DO_VOXEL(x0.w, x1.w, x2.w, tv.w);
#undef DO_VOXEL
        }

        float v[9] = { fi0, fi1, fi2, fp0, fp1, fp2, fc0, fc1, fc2 };
#pragma unroll
        for (int o = 16; o; o >>= 1)
#pragma unroll
            for (int q = 0; q < 9; q++)
                v[q] += __shfl_down_sync(0xffffffffu, v[q], o);

        __shared__ float red[8][9];
        int w = threadIdx.x >> 5, l = threadIdx.x & 31;
        if (l == 0)
#pragma unroll
            for (int q = 0; q < 9; q++) red[w][q] = v[q];
        __syncthreads();
        if (threadIdx.x < 9) {
            float s = 0.f;
#pragma unroll
            for (int w2 = 0; w2 < 8; w2++) s += red[w2][threadIdx.x];
            g_dpart[bid * 9 + threadIdx.x] = s;
        }
    } else {
        int gid = (bid - NDICE) * 256 + threadIdx.x;
        if (gid >= 2 * NPOS) return;
        int b = gid / NPOS, idx = gid % NPOS;
        const float* fmap;
        int D, s, N, n;
        if (idx < 4096)      { fmap = f0; D = 16; s = 8;  N = 4096; n = idx; }
        else if (idx < 4608) { fmap = f1; D = 8;  s = 16; N = 512;  n = idx - 4096; }
        else                 { fmap = f2; D = 4;  s = 32; N = 64;   n = idx - 4608; }

        __nv_bfloat16* dst = g_f + (size_t)gid * PADK;
        if (n >= N) {
            for (int c = 0; c < PADK; c++) dst[c] = __float2bfloat16(0.f);
            g_cls[gid] = 3;
            return;
        }
        int z = n / (D * D), y = (n / D) % D, x = n % D;
        int tv = tgt[(size_t)b * VOX + ((size_t)(z * s) * 128 + y * s) * 128 + x * s];
        int cls = tv < 0 ? 0 : (tv > 2 ? 2 : tv);
        g_cls[gid] = cls;

        float v[CCH];
        float ss = 0.f;
#pragma unroll
        for (int c = 0; c < CCH; c++) {
            v[c] = fmap[((size_t)b * CCH + c) * N + n];
            ss = fmaf(v[c], v[c], ss);
        }
        float inv = 1.f / fmaxf(sqrtf(ss), 1e-12f);
#pragma unroll
        for (int c = 0; c < CCH; c++) {
            float f = v[c] * inv;
            __nv_bfloat16 h = __float2bfloat16(f);
            dst[c]       = h;                                        // hi
            dst[48 + c]  = __float2bfloat16(f - __bfloat162float(h)); // lo
        }
        for (int c = KEXT; c < PADK; c++) dst[c] = __float2bfloat16(0.f);
    }
}

// ---------------- helpers ----------------
__device__ __forceinline__ float ex2f(float x) {
    float y;
    asm("ex2.approx.f32 %0, %1;" : "=f"(y) : "f"(x));
    return y;
}
__device__ __forceinline__ void mma16816(float* c, const uint32_t* a, const uint32_t* b) {
    asm volatile(
        "mma.sync.aligned.m16n8k16.row.col.f32.bf16.bf16.f32 "
        "{%0,%1,%2,%3}, {%4,%5,%6,%7}, {%8,%9}, {%0,%1,%2,%3};"
        : "+f"(c[0]), "+f"(c[1]), "+f"(c[2]), "+f"(c[3])
        : "r"(a[0]), "r"(a[1]), "r"(a[2]), "r"(a[3]), "r"(b[0]), "r"(b[1]));
}

// ====== kernel B: HMMA gram (hi/lo bf16, K=96) + ticketed finalize ======
__global__ void __launch_bounds__(256, 2)
gram_kernel(const float* __restrict__ logits,
            const int* __restrict__ labels,
            float* __restrict__ out) {
    int gid = blockIdx.x;
    int b, p, T, off;
    if (gid < 1056)      { b = gid / 528;  p = gid % 528; T = 32; off = 0; }
    else if (gid < 1076) { int l2 = gid - 1056; b = l2 / 10; p = l2 % 10; T = 4; off = 4096; }
    else                 { b = gid - 1076; p = 0; T = 1; off = 4608; }
    int by = 0;
    while (p >= T - by) { p -= T - by; by++; }
    int bx = by + p;

    extern __shared__ char smc[];
    __nv_bfloat16* As = (__nv_bfloat16*)smc;                  // [128][PADK]
    __nv_bfloat16* Bs = (__nv_bfloat16*)(smc + 128 * PADK * 2);
    float* wr = (float*)(smc + 2 * 128 * PADK * 2);           // [3][128]
    float* wc = wr + 3 * 128;

    int tid = threadIdx.x, wid = tid >> 5, lane = tid & 31;

    const uint4* GA = (const uint4*)(g_f + (size_t)(b * NPOS + off + by * 128) * PADK);
    const uint4* GB = (const uint4*)(g_f + (size_t)(b * NPOS + off + bx * 128) * PADK);
    for (int t = tid; t < 1664; t += 256) {
        ((uint4*)As)[t] = GA[t];
        ((uint4*)Bs)[t] = GB[t];
    }
    if (tid < 128) {
        int cr = g_cls[b * NPOS + off + by * 128 + tid];
        wr[tid]       = (cr == 0) ? 1.f : 0.f;
        wr[128 + tid] = (cr == 1) ? 1.f : 0.f;
        wr[256 + tid] = (cr == 2) ? 1.f : 0.f;
    } else {
        int t2 = tid - 128;
        int cc = g_cls[b * NPOS + off + bx * 128 + t2];
        wc[t2]       = (cc == 0) ? 1.f : 0.f;
        wc[128 + t2] = (cc == 1) ? 1.f : 0.f;
        wc[256 + t2] = (cc == 2) ? 1.f : 0.f;
    }
    __syncthreads();

    int warp_m = wid & 3, warp_n = wid >> 2;
    int qr = lane >> 2, qc = lane & 3;

    float acc[2][8][4];
#pragma unroll
    for (int mt = 0; mt < 2; mt++)
#pragma unroll
        for (int nt = 0; nt < 8; nt++)
#pragma unroll
            for (int e = 0; e < 4; e++) acc[mt][nt][e] = 0.f;

#pragma unroll
    for (int ks = 0; ks < 6; ks++) {
        int k0 = ks * 16 + qc * 2;
        uint32_t afr[2][4];
#pragma unroll
        for (int mt = 0; mt < 2; mt++) {
            int r = warp_m * 32 + mt * 16 + qr;
            afr[mt][0] = *(const uint32_t*)(As + r * PADK + k0);
            afr[mt][1] = *(const uint32_t*)(As + (r + 8) * PADK + k0);
            afr[mt][2] = *(const uint32_t*)(As + r * PADK + k0 + 8);
            afr[mt][3] = *(const uint32_t*)(As + (r + 8) * PADK + k0 + 8);
        }
#pragma unroll
        for (int nt = 0; nt < 8; nt++) {
            int n = warp_n * 64 + nt * 8 + qr;
            uint32_t bfr[2];
            bfr[0] = *(const uint32_t*)(Bs + n * PADK + k0);
            bfr[1] = *(const uint32_t*)(Bs + n * PADK + k0 + 8);
            mma16816(acc[0][nt], afr[0], bfr);
            mma16816(acc[1][nt], afr[1], bfr);
        }
    }

    // ---- epilogue ----
    const float L2E10 = 14.4269504088896340736f;
    bool diag = (by == bx);
    float lacc[9];
#pragma unroll
    for (int q = 0; q < 9; q++) lacc[q] = 0.f;

#pragma unroll
    for (int mt = 0; mt < 2; mt++) {
        int r0 = warp_m * 32 + mt * 16 + qr;
        int r1 = r0 + 8;
        float wA0 = wr[r0], wA1 = wr[128 + r0], wA2 = wr[256 + r0];
        float wB0 = wr[r1], wB1 = wr[128 + r1], wB2 = wr[256 + r1];
        float ra0 = 0.f, ra1 = 0.f, ra2 = 0.f;
        float rb0 = 0.f, rb1 = 0.f, rb2 = 0.f;
#pragma unroll
        for (int nt = 0; nt < 8; nt++) {
            int c0 = warp_n * 64 + nt * 8 + qc * 2;
            int c1 = c0 + 1;
            float u00 = wc[c0], u01 = wc[128 + c0], u02 = wc[256 + c0];
            float u10 = wc[c1], u11 = wc[128 + c1], u12 = wc[256 + c1];
            float E00 = ex2f(acc[mt][nt][0] * L2E10);
            float E01 = ex2f(acc[mt][nt][1] * L2E10);
            float E10 = ex2f(acc[mt][nt][2] * L2E10);
            float E11 = ex2f(acc[mt][nt][3] * L2E10);
            if (diag) {
                if (c0 <= r0) E00 = 0.f;
                if (c1 <= r0) E01 = 0.f;
                if (c0 <= r1) E10 = 0.f;
                if (c1 <= r1) E11 = 0.f;
            }
            ra0 = fmaf(E00, u00, fmaf(E01, u10, ra0));
            ra1 = fmaf(E00, u01, fmaf(E01, u11, ra1));
            ra2 = fmaf(E00, u02, fmaf(E01, u12, ra2));
            rb0 = fmaf(E10, u00, fmaf(E11, u10, rb0));
            rb1 = fmaf(E10, u01, fmaf(E11, u11, rb1));
            rb2 = fmaf(E10, u02, fmaf(E11, u12, rb2));
        }
        lacc[0] = fmaf(wA0, ra0, fmaf(wB0, rb0, lacc[0]));
        lacc[1] = fmaf(wA0, ra1, fmaf(wB0, rb1, lacc[1]));
        lacc[2] = fmaf(wA0, ra2, fmaf(wB0, rb2, lacc[2]));
        lacc[3] = fmaf(wA1, ra0, fmaf(wB1, rb0, lacc[3]));
        lacc[4] = fmaf(wA1, ra1, fmaf(wB1, rb1, lacc[4]));
        lacc[5] = fmaf(wA1, ra2, fmaf(wB1, rb2, lacc[5]));
        lacc[6] = fmaf(wA2, ra0, fmaf(wB2, rb0, lacc[6]));
        lacc[7] = fmaf(wA2, ra1, fmaf(wB2, rb1, lacc[7]));
        lacc[8] = fmaf(wA2, ra2, fmaf(wB2, rb2, lacc[8]));
    }

#pragma unroll
    for (int o = 16; o; o >>= 1)
#pragma unroll
        for (int q = 0; q < 9; q++)
            lacc[q] += __shfl_down_sync(0xffffffffu, lacc[q], o);

    __shared__ float rsum[8][9];
    if (lane == 0)
#pragma unroll
        for (int q = 0; q < 9; q++) rsum[wid][q] = lacc[q];
    __syncthreads();
    if (tid < 9) {
        float s = 0.f;
#pragma unroll
        for (int w2 = 0; w2 < 8; w2++) s += rsum[w2][tid];
        g_gpart[gid * 9 + tid] = s;
        __threadfence();
    }
    __syncthreads();

    __shared__ unsigned int amLast;
    if (tid == 0) amLast = (atomicAdd(&g_ticket, 1u) == NGRAM - 1) ? 1u : 0u;
    __syncthreads();
    if (!amLast) return;

    // ============== finalize (one block; parallel transcendentals) ==============
    __shared__ double sred[256];
    __shared__ double sdice[2][9];
    __shared__ double sgp[6][9];
    __shared__ int    scnt[18];
    __shared__ float  sterm[40];   // [0:30) pair, [30:36) focal, [36:40) dice

    for (int bb = 0; bb < 2; bb++) {
        double a[9];
#pragma unroll
        for (int q = 0; q < 9; q++) a[q] = 0.0;
        for (int i = bb * 1024 + tid; i < (bb + 1) * 1024; i += 256)
#pragma unroll
            for (int q = 0; q < 9; q++) a[q] += (double)g_dpart[i * 9 + q];
        for (int q = 0; q < 9; q++) {
            sred[tid] = a[q];
            __syncthreads();
            for (int s = 128; s; s >>= 1) {
                if (tid < s) sred[tid] += sred[tid + s];
                __syncthreads();
            }
            if (tid == 0) sdice[bb][q] = sred[0];
            __syncthreads();
        }
    }

    if (tid < 32) {
        const int gs[7] = { 0, 528, 1056, 1066, 1076, 1077, 1078 };
        for (int g = 0; g < 6; g++) {
            double v[9];
#pragma unroll
            for (int q = 0; q < 9; q++) v[q] = 0.0;
            for (int i = gs[g] + tid; i < gs[g + 1]; i += 32)
#pragma unroll
                for (int q = 0; q < 9; q++) v[q] += (double)g_gpart[i * 9 + q];
#pragma unroll
            for (int q = 0; q < 9; q++)
                for (int o = 16; o; o >>= 1)
                    v[q] += __shfl_down_sync(0xffffffffu, v[q], o);
            if (tid == 0)
#pragma unroll
                for (int q = 0; q < 9; q++) sgp[g][q] = v[q];
        }
    } else if (tid < 64) {
        int ll = tid - 32;
        int c[18];
#pragma unroll
        for (int k = 0; k < 18; k++) c[k] = 0;
        for (int i = ll; i < 2 * NPOS; i += 32) {
            int cls = g_cls[i];
            if (cls > 2) continue;
            int bb = i / NPOS, idx = i % NPOS;
            int sc = idx < 4096 ? 0 : (idx < 4608 ? 1 : 2);
            c[(bb * 3 + sc) * 3 + cls]++;
        }
#pragma unroll
        for (int k = 0; k < 18; k++)
            for (int o = 16; o; o >>= 1)
                c[k] += __shfl_down_sync(0xffffffffu, c[k], o);
        if (ll == 0)
#pragma unroll
            for (int k = 0; k < 18; k++) scnt[k] = c[k];
    }
    __syncthreads();

    // ---- parallel transcendental terms (float; rel err ~1e-7 << 1e-3) ----
    if (tid < 30) {
        int g = tid / 5, t5 = tid % 5;          // g = sc*2 + bb
        int sc = g >> 1, bb = g & 1;
        const double* Tt = sgp[g];
        const int* cc = scnt + (bb * 3 + sc) * 3;
        double c0 = cc[0], c1 = cc[1], c2 = cc[2];
        double S, cnt;
        bool positive;
        if (t5 == 0)      { S = 2.0 * Tt[4];   cnt = c1 * c1 - c1; positive = true;  }
        else if (t5 == 1) { S = 2.0 * Tt[8];   cnt = c2 * c2 - c2; positive = true;  }
        else if (t5 == 2) { S = Tt[5] + Tt[7]; cnt = c1 * c2;      positive = false; }
        else if (t5 == 3) { S = Tt[1] + Tt[3]; cnt = c0 * c1;      positive = false; }
        else              { S = Tt[2] + Tt[6]; cnt = c0 * c2;      positive = false; }
        float val = 0.f;
        if (cnt > 0.0) {
            float mean = (float)(S / (cnt < 1.0 ? 1.0 : cnt));
            val = positive ? -logf(mean + 1e-6f) : log1pf(mean);
        }
        sterm[tid] = val;
    } else if (tid >= 32 && tid < 38) {
        int i = tid - 32;
        float x  = logits[i];
        float pt = __fdividef(1.f, 1.f + __expf(-x));
        if (labels[i] != 1) pt = 1.f - pt;
        float om = 1.f - pt;
        sterm[30 + i] = -0.25f * om * om * logf(pt + 1e-6f);
    } else if (tid >= 40 && tid < 44) {
        int i = tid - 40;
        int bb = i >> 1, c = (i & 1) + 1;
        double inter = sdice[bb][c];
        double psum  = sdice[bb][3 + c];
        double vcnt  = sdice[bb][6 + c];
        sterm[36 + i] = (float)((2.0 * inter + 1e-5) / (psum + vcnt + 1e-5));
    }
    __syncthreads();

    if (tid == 0) {
        float dice = 1.f - 0.25f * (sterm[36] + sterm[37] + sterm[38] + sterm[39]);
        float focal = (sterm[30] + sterm[31] + sterm[32] +
                       sterm[33] + sterm[34] + sterm[35]) * (1.f / 6.f);
        const float wsc[3] = { 1.f, 0.8f, 0.6f };
        float contr = 0.f;
#pragma unroll
        for (int sc = 0; sc < 3; sc++) {
            float sl = 0.f;
#pragma unroll
            for (int g = sc * 2; g < sc * 2 + 2; g++)
#pragma unroll
                for (int t5 = 0; t5 < 5; t5++) sl += sterm[g * 5 + t5];
            contr += wsc[sc] * (sl * 0.5f);
        }
        out[0] = dice + focal + 0.1f * contr;
        out[1] = dice;
        out[2] = focal;
        out[3] = contr;
    }
}

// ================= launcher =================
extern "C" void kernel_launch(void* const* d_in, const int* in_sizes, int n_in,
                              void* d_out, int out_size) {
    const float* pred   = (const float*)d_in[0];
    const int*   tgt    = (const int*)d_in[1];
    const float* f0     = (const float*)d_in[2];
    const float* f1     = (const float*)d_in[3];
    const float* f2     = (const float*)d_in[4];
    const float* logits = (const float*)d_in[5];
    const int*   labels = (const int*)d_in[6];
    float*       out    = (float*)d_out;

    const int smemBytes = 2 * 128 * PADK * 2 + 6 * 128 * 4;
    cudaFuncSetAttribute(gram_kernel,
                         cudaFuncAttributeMaxDynamicSharedMemorySize, smemBytes);

    diceprep_kernel<<<NDICE + 37, 256>>>(pred, tgt, f0, f1, f2);
    gram_kernel<<<NGRAM, 256, smemBytes>>>(logits, labels, out);
}